// round 5
// baseline (speedup 1.0000x reference)
#include <cuda_runtime.h>
#include <math.h>

// Problem dims (fixed)
#define B_   128
#define T_   500
#define NI_  256
#define N_   256
#define M_   (B_*T_)
#define TBN_ ((size_t)T_*B_*N_)

// xw scratch, m-pair interleaved: ULL index p*256+n holds (xw[2p][n], xw[2p+1][n])
__device__ unsigned long long g_xw[(size_t)M_ * N_ / 2];

// Packed fp32x2 helpers
#define FFMA2(d, a, b, c) \
    asm("fma.rn.f32x2 %0, %1, %2, %3;" : "=l"(d) : "l"(a), "l"(b), "l"(c))
#define PACK2(d, s) \
    asm("mov.b64 %0, {%1, %1};" : "=l"(d) : "f"(s))

// ===========================================================================
// Kernel 1: xw = x @ w_in (R2/R4 version, verbatim: measured ~189us).
// ===========================================================================
#define ASTRIDE 132
#define ASZ (2*16*ASTRIDE)
#define BSZ (2*16*256)
#define GEMM_SMEM ((ASZ + BSZ) * 4)

__global__ void __launch_bounds__(256, 1)
gemm_xw(const float* __restrict__ A, const float* __restrict__ W)
{
    extern __shared__ float gsm[];
    float* As = gsm;          // [2][16][132]
    float* Bs = gsm + ASZ;    // [2][16][256]

    const int t  = threadIdx.x;
    const int bm = blockIdx.x << 7;
    const int tm = t >> 4, tn = t & 15;
    const int m0 = tm << 3;

    const int amr[2] = { (t) >> 2, (t + 256) >> 2 };
    const int akc[2] = { (t & 3) << 2, (t & 3) << 2 };

    unsigned long long acc[4][16];
#pragma unroll
    for (int e = 0; e < 4; e++)
#pragma unroll
        for (int j = 0; j < 16; j++) acc[e][j] = 0ull;

    float4 ra[2];

#pragma unroll
    for (int i = 0; i < 2; i++)
        ra[i] = *(const float4*)(A + (size_t)(bm + amr[i]) * NI_ + akc[i]);
#pragma unroll
    for (int i = 0; i < 4; i++) {
        int id = t + (i << 8), bk = id >> 6, bn = (id & 63) << 2;
        unsigned dst = (unsigned)__cvta_generic_to_shared(Bs + bk * 256 + bn);
        asm volatile("cp.async.cg.shared.global [%0], [%1], 16;"
                     :: "r"(dst), "l"(W + (size_t)bk * N_ + bn));
    }
    asm volatile("cp.async.commit_group;");
#pragma unroll
    for (int i = 0; i < 2; i++) {
        As[(akc[i] + 0) * ASTRIDE + amr[i]] = ra[i].x;
        As[(akc[i] + 1) * ASTRIDE + amr[i]] = ra[i].y;
        As[(akc[i] + 2) * ASTRIDE + amr[i]] = ra[i].z;
        As[(akc[i] + 3) * ASTRIDE + amr[i]] = ra[i].w;
    }
    asm volatile("cp.async.wait_group 0;");
    __syncthreads();

    for (int kt = 0; kt < 16; kt++) {
        const int st = kt & 1;
        if (kt < 15) {
#pragma unroll
            for (int i = 0; i < 2; i++)
                ra[i] = *(const float4*)(A + (size_t)(bm + amr[i]) * NI_
                                           + (kt + 1) * 16 + akc[i]);
#pragma unroll
            for (int i = 0; i < 4; i++) {
                int id = t + (i << 8), bk = id >> 6, bn = (id & 63) << 2;
                unsigned dst = (unsigned)__cvta_generic_to_shared(
                    Bs + (st ^ 1) * (16 * 256) + bk * 256 + bn);
                asm volatile("cp.async.cg.shared.global [%0], [%1], 16;"
                    :: "r"(dst), "l"(W + (size_t)((kt+1)*16 + bk) * N_ + bn));
            }
            asm volatile("cp.async.commit_group;");
        }

        const float* as = As + st * (16 * ASTRIDE);
        const float* bs = Bs + st * (16 * 256);
#pragma unroll
        for (int k = 0; k < 16; k++) {
            ulonglong2 aA = *(const ulonglong2*)(as + k * ASTRIDE + m0);
            ulonglong2 aB = *(const ulonglong2*)(as + k * ASTRIDE + m0 + 4);
            unsigned long long am4[4] = { aA.x, aA.y, aB.x, aB.y };
#pragma unroll
            for (int c = 0; c < 4; c++) {
                float4 bv = *(const float4*)(bs + k * 256 + (c << 6) + (tn << 2));
                unsigned long long b0, b1, b2, b3;
                PACK2(b0, bv.x); PACK2(b1, bv.y);
                PACK2(b2, bv.z); PACK2(b3, bv.w);
#pragma unroll
                for (int e = 0; e < 4; e++) {
                    FFMA2(acc[e][4*c+0], am4[e], b0, acc[e][4*c+0]);
                    FFMA2(acc[e][4*c+1], am4[e], b1, acc[e][4*c+1]);
                    FFMA2(acc[e][4*c+2], am4[e], b2, acc[e][4*c+2]);
                    FFMA2(acc[e][4*c+3], am4[e], b3, acc[e][4*c+3]);
                }
            }
        }
        if (kt == 15) break;

#pragma unroll
        for (int i = 0; i < 2; i++) {
            float* ad = As + (st ^ 1) * (16 * ASTRIDE);
            ad[(akc[i] + 0) * ASTRIDE + amr[i]] = ra[i].x;
            ad[(akc[i] + 1) * ASTRIDE + amr[i]] = ra[i].y;
            ad[(akc[i] + 2) * ASTRIDE + amr[i]] = ra[i].z;
            ad[(akc[i] + 3) * ASTRIDE + amr[i]] = ra[i].w;
        }
        asm volatile("cp.async.wait_group 0;");
        __syncthreads();
    }

    unsigned long long* op = g_xw;
    const int pbase = (bm + m0) >> 1;
#pragma unroll
    for (int e = 0; e < 4; e++) {
        size_t prow = (size_t)(pbase + e) * 256;
#pragma unroll
        for (int c = 0; c < 4; c++) {
            int ncol = (c << 6) + (tn << 2);
            ulonglong2 s0, s1;
            s0.x = acc[e][4*c+0]; s0.y = acc[e][4*c+1];
            s1.x = acc[e][4*c+2]; s1.y = acc[e][4*c+3];
            *(ulonglong2*)(op + prow + ncol)     = s0;
            *(ulonglong2*)(op + prow + ncol + 2) = s1;
        }
    }
}

// ===========================================================================
// Kernel 2: LSNN scan, 2 batches per CTA (64 CTAs x 512 threads).
// Half h (256 threads) runs batch 2*blockIdx.x+h; both halves share the
// 224 smem weight rows + zero sentinel row 224. Active lists are u8 row
// indices (sentinel = 224), double buffered per half. Gather arithmetic is
// bit-identical to R4's block-read version.
// ===========================================================================
#define WROWS 224
#define SENTB 224
#define LCAP  288     // bytes per list buffer (tot<=256 + 32 sentinel pad)
#define SCAN_SMEM (225*256*4 + 2*2*LCAP + 32*4 + 4*4 + 4*4)   // 231840 B

__global__ void __launch_bounds__(512, 1)
lsnn_scan(const float* __restrict__ w_rec,
          const float* __restrict__ z0,  const float* __restrict__ v0,
          const float* __restrict__ a0,  const float* __restrict__ lsd0,
          float* __restrict__ out, float decay_v, float decay_a)
{
    extern __shared__ float sm[];
    float*         w_sm  = sm;                                // [225][256]
    unsigned char* listB = (unsigned char*)(sm + 225 * 256);  // [2 half][2 buf][288]
    int*           cntS  = (int*)(listB + 2 * 2 * LCAP);      // [2 half][2 buf][8]
    unsigned*      maskS = (unsigned*)(cntS + 32);            // [2 half][2 buf]
    int*           totS  = (int*)(maskS + 4);                 // [2 half][2 buf]

    const int tid   = threadIdx.x;
    const int half  = tid >> 8;
    const int n     = tid & 255;
    const int w     = (tid >> 5) & 7;    // warp within half
    const int lane  = tid & 31;
    const int bglob = (blockIdx.x << 1) + half;

    // per-half views
    unsigned char* listH = listB + half * (2 * LCAP);
    int*           cntH  = cntS + half * 16;
    unsigned*      maskH = maskS + half * 2;
    int*           totH  = totS + half * 2;

    // weights rows 0..223 -> smem (all 512 threads)
    {
        const float4* src = (const float4*)w_rec;
        float4*       dst = (float4*)w_sm;
        for (int i = tid; i < WROWS * 64; i += 512) dst[i] = src[i];
    }
    // rows 224..255 -> regs (per thread; column n), diag masked
    float wreg[32];
#pragma unroll
    for (int j = 0; j < 32; j++) wreg[j] = w_rec[(WROWS + j) * 256 + n];
#pragma unroll
    for (int j = 0; j < 32; j++)
        if (n == WROWS + j) wreg[j] = 0.f;
    if (half == 0) w_sm[224 * 256 + n] = 0.f;   // zero sentinel row
    if (tid < 32) cntS[tid] = 0;                // zero all counts (incl. slot 7)
    __syncthreads();
    if (tid < WROWS) w_sm[tid * 256 + tid] = 0.f;   // diag mask

    float z_self = z0[bglob * N_ + n];
    float v      = v0[bglob * N_ + n];
    float a      = a0[bglob * N_ + n];
    float lsd    = lsd0[bglob * N_ + n];

    // initial list build (buffer 0) per half
    unsigned mB = __ballot_sync(0xffffffffu, z_self != 0.f);
    if (w < 7) { if (lane == 0) cntH[w] = __popc(mB); }
    else if (lane == 0) maskH[0] = mB;
    __syncthreads();
    {
        int4 cA = *(const int4*)&cntH[0];
        int4 cB = *(const int4*)&cntH[4];
        if (w < 7) {
            int start = 0;
            if (w > 0) start += cA.x; if (w > 1) start += cA.y;
            if (w > 2) start += cA.z; if (w > 3) start += cA.w;
            if (w > 4) start += cB.x; if (w > 5) start += cB.y;
            if (z_self != 0.f) {
                int r = __popc(mB & ((1u << lane) - 1u));
                listH[start + r] = (unsigned char)n;
            }
        } else {
            int tt = cA.x + cA.y + cA.z + cA.w + cB.x + cB.y + cB.z;
            listH[tt + lane] = (unsigned char)SENTB;   // 32 sentinels
            if (lane == 0) totH[0] = tt;
        }
    }

    const float omdv = 1.f - decay_v;
    const float omda = 1.f - decay_a;
    const char*  wpn = (const char*)w_sm + (n << 2);
    const float* xwb = (const float*)g_xw;
    const int    mb0 = bglob * T_;
    const int    twon = n << 1;

    float xw_cur = __ldcs(xwb + (((size_t)(mb0 >> 1)) << 9) + twon + (mb0 & 1));
    __syncthreads();

// gather 4 entries packed in one u32 word, into av[q..q+3]
#define GW(wd, q) do { unsigned wd_ = (unsigned)(wd);                       \
    av[(q)+0] += *(const float*)(wpn + ((wd_ & 255u) << 10));               \
    av[(q)+1] += *(const float*)(wpn + (((wd_ >> 8) & 255u) << 10));        \
    av[(q)+2] += *(const float*)(wpn + (((wd_ >> 16) & 255u) << 10));       \
    av[(q)+3] += *(const float*)(wpn + ((wd_ >> 24) << 10)); } while (0)

#pragma unroll 1
    for (int t = 0; t < T_; t++) {
        const int rb = t & 1, wb = rb ^ 1;

        float xw_next = 0.f;
        if (t + 1 < T_) {
            int mn = mb0 + t + 1;
            xw_next = __ldcs(xwb + (((size_t)(mn >> 1)) << 9) + twon + (mn & 1));
        }

        const int      tot = totH[rb];
        const unsigned mh  = maskH[rb];
        const unsigned char* fl = listH + rb * LCAP;

        // block read: 32 u8 entries as two int4 broadcasts
        int4 ca = *(const int4*)fl;
        int4 cb = *(const int4*)(fl + 16);

        float av[8];
#pragma unroll
        for (int j = 0; j < 8; j++) av[j] = 0.f;

        // register-held high rows (fill load latency)
#pragma unroll
        for (int j = 0; j < 32; j++)
            if (mh & (1u << j)) av[j & 7] += wreg[j];

        GW(ca.x, 0); GW(ca.y, 4); GW(ca.z, 0); GW(ca.w, 4);
        GW(cb.x, 0); GW(cb.y, 4); GW(cb.z, 0); GW(cb.w, 4);

        // rare tail (tot > 32); sentinel-padded 32 beyond tot
#pragma unroll 1
        for (int j = 32; j < tot; j += 4) {
            unsigned wd = *(const unsigned*)(fl + j);
            GW(wd, 0);
        }

        const float i_in = __fadd_rn(xw_cur,
            __fadd_rn(__fadd_rn(__fadd_rn(av[0], av[1]), __fadd_rn(av[2], av[3])),
                      __fadd_rn(__fadd_rn(av[4], av[5]), __fadd_rn(av[6], av[7]))));

        // dynamics; spike via compare (thr > 0), div off critical path
        float new_a = __fadd_rn(__fmul_rn(decay_a, a), __fmul_rn(omda, z_self));
        float thr   = __fadd_rn(0.03f, __fmul_rn(new_a, 1.8f));
        float new_v = __fadd_rn(
                        __fadd_rn(__fmul_rn(decay_v, v), __fmul_rn(omdv, i_in)),
                        __fmul_rn(-thr, z_self));
        int   spk = (new_v > thr) && (lsd >= 2.f);
        float zf  = spk ? 1.f : 0.f;

        // phase 1: publish counts / high mask
        unsigned m = __ballot_sync(0xffffffffu, spk);
        if (w < 7) { if (lane == 0) cntH[wb * 8 + w] = __popc(m); }
        else if (lane == 0) maskH[wb] = m;

        float new_lsd = __fmul_rn(__fadd_rn(lsd, 1.f), __fadd_rn(1.f, -zf));
        float v_sc    = __fdividef(__fadd_rn(new_v, -thr), thr);
        __syncthreads();

        // outputs [4, T, B, N]
        const size_t ob = ((size_t)t * B_ + bglob) * N_ + n;
        __stcs(out + ob,            zf);
        __stcs(out + TBN_ + ob,     new_v);
        __stcs(out + 2 * TBN_ + ob, thr);
        __stcs(out + 3 * TBN_ + ob, v_sc);

        // phase 2: prefix + u8 entry writes + sentinels
        {
            int4 cA = *(const int4*)&cntH[wb * 8];
            int4 cB = *(const int4*)&cntH[wb * 8 + 4];
            if (w < 7) {
                int start = 0;
                if (w > 0) start += cA.x; if (w > 1) start += cA.y;
                if (w > 2) start += cA.z; if (w > 3) start += cA.w;
                if (w > 4) start += cB.x; if (w > 5) start += cB.y;
                if (spk) {
                    int r = __popc(m & ((1u << lane) - 1u));
                    listH[wb * LCAP + start + r] = (unsigned char)n;
                }
            } else {
                int tt = cA.x + cA.y + cA.z + cA.w + cB.x + cB.y + cB.z;
                listH[wb * LCAP + tt + lane] = (unsigned char)SENTB;
                if (lane == 0) totH[wb] = tt;
            }
        }

        z_self = zf; v = new_v; a = new_a; lsd = new_lsd;
        xw_cur = xw_next;
        __syncthreads();
    }
#undef GW
}

// ---------------------------------------------------------------------------
// Launcher (graph-capturable)
// ---------------------------------------------------------------------------
extern "C" void kernel_launch(void* const* d_in, const int* in_sizes, int n_in,
                              void* d_out, int out_size)
{
    const float* x     = (const float*)d_in[0];
    const float* w_in  = (const float*)d_in[1];
    const float* w_rec = (const float*)d_in[2];
    const float* z0    = (const float*)d_in[3];
    const float* v0    = (const float*)d_in[4];
    const float* a0    = (const float*)d_in[5];
    const float* lsd0  = (const float*)d_in[6];
    float* out = (float*)d_out;

    const float decay_v = expf(-1.0f / 20.0f);
    const float decay_a = expf(-1.0f / 20.0f);

    cudaFuncSetAttribute(gemm_xw,
                         cudaFuncAttributeMaxDynamicSharedMemorySize, GEMM_SMEM);
    cudaFuncSetAttribute(lsnn_scan,
                         cudaFuncAttributeMaxDynamicSharedMemorySize, SCAN_SMEM);

    gemm_xw<<<M_ / 128, 256, GEMM_SMEM>>>(x, w_in);
    lsnn_scan<<<B_ / 2, 512, SCAN_SMEM>>>(w_rec, z0, v0, a0, lsd0, out,
                                          decay_v, decay_a);
}

// round 7
// speedup vs baseline: 1.4774x; 1.4774x over previous
#include <cuda_runtime.h>
#include <math.h>

// Problem dims (fixed)
#define B_   128
#define T_   500
#define NI_  256
#define N_   256
#define M_   (B_*T_)
#define TBN_ ((size_t)T_*B_*N_)

// xw scratch, m-pair interleaved: ULL index p*256+n holds (xw[2p][n], xw[2p+1][n])
__device__ unsigned long long g_xw[(size_t)M_ * N_ / 2];

// Packed fp32x2 helpers
#define FFMA2(d, a, b, c) \
    asm("fma.rn.f32x2 %0, %1, %2, %3;" : "=l"(d) : "l"(a), "l"(b), "l"(c))
#define PACK2(d, s) \
    asm("mov.b64 %0, {%1, %1};" : "=l"(d) : "f"(s))
#define PACKAB(d, lo, hi) \
    asm("mov.b64 %0, {%1, %2};" : "=l"(d) : "f"(lo), "f"(hi))

// ===========================================================================
// Kernel 1: xw = x @ w_in. BM=128, BN=128, BK=16, 256 thr, 8m x 8n microtile.
// 2 CTAs/SM (regs capped at 128) for latency hiding.
// ===========================================================================
#define ASTRIDE 132
#define ASZ (2*16*ASTRIDE)          // floats
#define BSZ (2*16*128)              // floats
#define GEMM_SMEM ((ASZ + BSZ) * 4) // 33280 B

__global__ void __launch_bounds__(256, 2)
gemm_xw(const float* __restrict__ A, const float* __restrict__ W)
{
    extern __shared__ float gsm[];
    float* As = gsm;          // [2][16][132]
    float* Bs = gsm + ASZ;    // [2][16][128]

    const int t   = threadIdx.x;
    const int bm  = blockIdx.x << 7;
    const int bn0 = blockIdx.y << 7;
    const int tn  = t & 15;
    const int m0  = (t >> 4) << 3;

    const int amr[2] = { (t) >> 2, (t + 256) >> 2 };
    const int akc    = (t & 3) << 2;
    // B loads: i in {0,1}: id = t + 256i -> bk = id>>5, bn = (id&31)*4
    const int bkr[2] = { t >> 5, (t + 256) >> 5 };
    const int bnc    = (t & 31) << 2;

    unsigned long long acc[4][8];
#pragma unroll
    for (int e = 0; e < 4; e++)
#pragma unroll
        for (int j = 0; j < 8; j++) acc[e][j] = 0ull;

    float4 ra[2];

    // prologue: k-tile 0
#pragma unroll
    for (int i = 0; i < 2; i++)
        ra[i] = *(const float4*)(A + (size_t)(bm + amr[i]) * NI_ + akc);
#pragma unroll
    for (int i = 0; i < 2; i++) {
        unsigned dst = (unsigned)__cvta_generic_to_shared(Bs + bkr[i] * 128 + bnc);
        asm volatile("cp.async.cg.shared.global [%0], [%1], 16;"
                     :: "r"(dst), "l"(W + (size_t)bkr[i] * N_ + bn0 + bnc));
    }
    asm volatile("cp.async.commit_group;");
#pragma unroll
    for (int i = 0; i < 2; i++) {
        As[(akc + 0) * ASTRIDE + amr[i]] = ra[i].x;
        As[(akc + 1) * ASTRIDE + amr[i]] = ra[i].y;
        As[(akc + 2) * ASTRIDE + amr[i]] = ra[i].z;
        As[(akc + 3) * ASTRIDE + amr[i]] = ra[i].w;
    }
    asm volatile("cp.async.wait_group 0;");
    __syncthreads();

    for (int kt = 0; kt < 16; kt++) {
        const int st = kt & 1;
        if (kt < 15) {
#pragma unroll
            for (int i = 0; i < 2; i++)
                ra[i] = *(const float4*)(A + (size_t)(bm + amr[i]) * NI_
                                           + (kt + 1) * 16 + akc);
#pragma unroll
            for (int i = 0; i < 2; i++) {
                unsigned dst = (unsigned)__cvta_generic_to_shared(
                    Bs + (st ^ 1) * (16 * 128) + bkr[i] * 128 + bnc);
                asm volatile("cp.async.cg.shared.global [%0], [%1], 16;"
                    :: "r"(dst),
                       "l"(W + (size_t)((kt+1)*16 + bkr[i]) * N_ + bn0 + bnc));
            }
            asm volatile("cp.async.commit_group;");
        }

        const float* as = As + st * (16 * ASTRIDE);
        const float* bs = Bs + st * (16 * 128);
#pragma unroll
        for (int k = 0; k < 16; k++) {
            ulonglong2 aA = *(const ulonglong2*)(as + k * ASTRIDE + m0);
            ulonglong2 aB = *(const ulonglong2*)(as + k * ASTRIDE + m0 + 4);
            unsigned long long am4[4] = { aA.x, aA.y, aB.x, aB.y };
            float4 bv0 = *(const float4*)(bs + k * 128 + (tn << 2));
            float4 bv1 = *(const float4*)(bs + k * 128 + 64 + (tn << 2));
            unsigned long long b[8];
            PACK2(b[0], bv0.x); PACK2(b[1], bv0.y);
            PACK2(b[2], bv0.z); PACK2(b[3], bv0.w);
            PACK2(b[4], bv1.x); PACK2(b[5], bv1.y);
            PACK2(b[6], bv1.z); PACK2(b[7], bv1.w);
#pragma unroll
            for (int e = 0; e < 4; e++)
#pragma unroll
                for (int j = 0; j < 8; j++)
                    FFMA2(acc[e][j], am4[e], b[j], acc[e][j]);
        }
        if (kt == 15) break;

#pragma unroll
        for (int i = 0; i < 2; i++) {
            float* ad = As + (st ^ 1) * (16 * ASTRIDE);
            ad[(akc + 0) * ASTRIDE + amr[i]] = ra[i].x;
            ad[(akc + 1) * ASTRIDE + amr[i]] = ra[i].y;
            ad[(akc + 2) * ASTRIDE + amr[i]] = ra[i].z;
            ad[(akc + 3) * ASTRIDE + amr[i]] = ra[i].w;
        }
        asm volatile("cp.async.wait_group 0;");
        __syncthreads();
    }

    // epilogue: pair-interleaved g_xw
    unsigned long long* op = g_xw;
    const int pbase = (bm + m0) >> 1;
#pragma unroll
    for (int e = 0; e < 4; e++) {
        size_t prow = (size_t)(pbase + e) * 256 + bn0;
        ulonglong2 s0, s1, s2, s3;
        s0.x = acc[e][0]; s0.y = acc[e][1];
        s1.x = acc[e][2]; s1.y = acc[e][3];
        s2.x = acc[e][4]; s2.y = acc[e][5];
        s3.x = acc[e][6]; s3.y = acc[e][7];
        *(ulonglong2*)(op + prow + (tn << 2))          = s0;
        *(ulonglong2*)(op + prow + (tn << 2) + 2)      = s1;
        *(ulonglong2*)(op + prow + 64 + (tn << 2))     = s2;
        *(ulonglong2*)(op + prow + 64 + (tn << 2) + 2) = s3;
    }
}

// ===========================================================================
// Kernel 2: LSNN scan (R4 skeleton, 128 CTAs x 256 thr).
//  - w_rec rows [0,222) + zero sentinel row 222 in smem (223 KB).
//  - Rows 222..255 (34 rows) handled DENSELY: spiking threads stage zf into a
//    34-float smem vector; gather does 17 broadcast LDS.64 + 17 FFMA2 against
//    pre-packed register weight pairs (products exact: z in {0,1}).
//  - Main active list (rows < 222 only), block-read 32 + sentinel pad + tail.
//  - xw software pipeline depth 2.
// ===========================================================================
#define WROWS 222
#define SENT  (222 << 10)
#define LCAP  232
// layout (floats): w_sm 223*256 | flatL 2*232 ints | cntS 16 ints | totS 2+2 pad | zhi 2*36
#define OFF_FLAT (223*256)
#define OFF_CNT  (OFF_FLAT + 2*LCAP)
#define OFF_TOT  (OFF_CNT + 16)
#define OFF_ZHI  (OFF_TOT + 4)
#define SCAN_SMEM ((OFF_ZHI + 2*36) * 4)    // 230608 B

__global__ void __launch_bounds__(256, 1)
lsnn_scan(const float* __restrict__ w_rec,
          const float* __restrict__ z0,  const float* __restrict__ v0,
          const float* __restrict__ a0,  const float* __restrict__ lsd0,
          float* __restrict__ out, float decay_v, float decay_a)
{
    extern __shared__ float sm[];
    float* w_sm  = sm;                       // [223][256], row 222 = zeros
    int*   flatL = (int*)(sm + OFF_FLAT);    // [2][232]
    int*   cntS  = (int*)(sm + OFF_CNT);     // [2][8]
    int*   totS  = (int*)(sm + OFF_TOT);     // [2]
    float* zhi   = sm + OFF_ZHI;             // [2][36] (34 used, pairs aligned)

    const int b    = blockIdx.x;
    const int n    = threadIdx.x;
    const int w    = n >> 5;
    const int lane = n & 31;

    // weights rows 0..221 -> smem
    {
        const float4* src = (const float4*)w_rec;
        float4*       dst = (float4*)w_sm;
        for (int i = n; i < WROWS * 64; i += 256) dst[i] = src[i];
    }
    // rows 222..255 -> packed register pairs (17 x f32x2), diag masked
    unsigned long long wp[17];
#pragma unroll
    for (int j = 0; j < 17; j++) {
        float wlo = w_rec[(size_t)(222 + 2*j) * 256 + n];
        float whi = w_rec[(size_t)(223 + 2*j) * 256 + n];
        if (n == 222 + 2*j) wlo = 0.f;
        if (n == 223 + 2*j) whi = 0.f;
        PACKAB(wp[j], wlo, whi);
    }
    w_sm[WROWS * 256 + n] = 0.f;             // zero sentinel row
    if (n < 16) cntS[n] = 0;
    if (n < 2)  totS[n] = 0;
    if (n < 72) zhi[n] = 0.f;
    __syncthreads();
    if (n < WROWS) w_sm[n * 256 + n] = 0.f;  // diag mask for smem rows

    float z_self = z0[b * N_ + n];
    float v      = v0[b * N_ + n];
    float a      = a0[b * N_ + n];
    float lsd    = lsd0[b * N_ + n];

    // initial build (buffer 0)
    {
        unsigned m    = __ballot_sync(0xffffffffu, z_self != 0.f);
        unsigned mseg = (w == 6) ? (m & 0x3FFFFFFFu) : m;   // rows >=222 excluded
        if (w < 7) { if (lane == 0) cntS[w] = __popc(mseg); }
        if (n >= 222) zhi[n - 222] = z_self;
        __syncthreads();
        int4 cA = *(const int4*)&cntS[0];
        int4 cB = *(const int4*)&cntS[4];
        if (w < 7) {
            int start = 0;
            if (w > 0) start += cA.x; if (w > 1) start += cA.y;
            if (w > 2) start += cA.z; if (w > 3) start += cA.w;
            if (w > 4) start += cB.x; if (w > 5) start += cB.y;
            if ((mseg >> lane) & 1u) {
                int r = __popc(mseg & ((1u << lane) - 1u));
                flatL[start + r] = n << 10;
            }
        }
        if (w == 7) {
            int tt = cA.x + cA.y + cA.z + cA.w + cB.x + cB.y + cB.z;
            if (lane < 8 || tt + lane < 32) flatL[tt + lane] = SENT;
            if (lane == 0) totS[0] = tt;
        }
    }

    const float omdv = 1.f - decay_v;
    const float omda = 1.f - decay_a;
    const char*  wpn = (const char*)w_sm + (n << 2);
    const float* xwb = (const float*)g_xw;
    const int    mb0 = b * T_;
    const int    twon = n << 1;

#define XW_LD(tt_) __ldcs(xwb + (((size_t)((mb0 + (tt_)) >> 1)) << 9) + twon + ((mb0 + (tt_)) & 1))
    float xw_c  = XW_LD(0);
    float xw_n1 = XW_LD(1);
    __syncthreads();

#pragma unroll 1
    for (int t = 0; t < T_; t++) {
        const int rb = t & 1, wb = rb ^ 1;

        float xw_n2 = (t + 2 < T_) ? XW_LD(t + 2) : 0.f;

        const int  tot = totS[rb];
        const int* fl  = flatL + rb * LCAP;
        const unsigned long long* zp =
            (const unsigned long long*)(zhi + rb * 36);

        const int4* fc = (const int4*)fl;
        int4 c0 = fc[0], c1 = fc[1], c2 = fc[2], c3 = fc[3];
        int4 c4 = fc[4], c5 = fc[5], c6 = fc[6], c7 = fc[7];

        float av[8];
#pragma unroll
        for (int j = 0; j < 8; j++) av[j] = 0.f;

        // dense high-row dot: 17 broadcast pairs x packed reg weights
        unsigned long long av2; PACKAB(av2, 0.f, 0.f);
#pragma unroll
        for (int j = 0; j < 17; j++) FFMA2(av2, zp[j], wp[j], av2);

        // 32 independent main-list loads (sentinels add exact 0)
        av[0] += *(const float*)(wpn + c0.x);
        av[1] += *(const float*)(wpn + c0.y);
        av[2] += *(const float*)(wpn + c0.z);
        av[3] += *(const float*)(wpn + c0.w);
        av[4] += *(const float*)(wpn + c1.x);
        av[5] += *(const float*)(wpn + c1.y);
        av[6] += *(const float*)(wpn + c1.z);
        av[7] += *(const float*)(wpn + c1.w);
        av[0] += *(const float*)(wpn + c2.x);
        av[1] += *(const float*)(wpn + c2.y);
        av[2] += *(const float*)(wpn + c2.z);
        av[3] += *(const float*)(wpn + c2.w);
        av[4] += *(const float*)(wpn + c3.x);
        av[5] += *(const float*)(wpn + c3.y);
        av[6] += *(const float*)(wpn + c3.z);
        av[7] += *(const float*)(wpn + c3.w);
        av[0] += *(const float*)(wpn + c4.x);
        av[1] += *(const float*)(wpn + c4.y);
        av[2] += *(const float*)(wpn + c4.z);
        av[3] += *(const float*)(wpn + c4.w);
        av[4] += *(const float*)(wpn + c5.x);
        av[5] += *(const float*)(wpn + c5.y);
        av[6] += *(const float*)(wpn + c5.z);
        av[7] += *(const float*)(wpn + c5.w);
        av[0] += *(const float*)(wpn + c6.x);
        av[1] += *(const float*)(wpn + c6.y);
        av[2] += *(const float*)(wpn + c6.z);
        av[3] += *(const float*)(wpn + c6.w);
        av[4] += *(const float*)(wpn + c7.x);
        av[5] += *(const float*)(wpn + c7.y);
        av[6] += *(const float*)(wpn + c7.z);
        av[7] += *(const float*)(wpn + c7.w);

        // rare tail (tot > 32); sentinel-padded beyond tot
#pragma unroll 1
        for (int j = 32; j < tot; j += 4) {
            int4 o = *(const int4*)(fl + j);
            av[0] += *(const float*)(wpn + o.x);
            av[1] += *(const float*)(wpn + o.y);
            av[2] += *(const float*)(wpn + o.z);
            av[3] += *(const float*)(wpn + o.w);
        }

        float2 hv = *(float2*)&av2;
        const float i_in = __fadd_rn(__fadd_rn(xw_c, __fadd_rn(hv.x, hv.y)),
            __fadd_rn(__fadd_rn(__fadd_rn(av[0], av[1]), __fadd_rn(av[2], av[3])),
                      __fadd_rn(__fadd_rn(av[4], av[5]), __fadd_rn(av[6], av[7]))));

        // dynamics; spike via compare (thr > 0), div off critical path
        float new_a = __fadd_rn(__fmul_rn(decay_a, a), __fmul_rn(omda, z_self));
        float thr   = __fadd_rn(0.03f, __fmul_rn(new_a, 1.8f));
        float new_v = __fadd_rn(
                        __fadd_rn(__fmul_rn(decay_v, v), __fmul_rn(omdv, i_in)),
                        __fmul_rn(-thr, z_self));
        int   spk = (new_v > thr) && (lsd >= 2.f);
        float zf  = spk ? 1.f : 0.f;

        // phase 1: counts + high-row z staging
        unsigned m    = __ballot_sync(0xffffffffu, spk);
        unsigned mseg = (w == 6) ? (m & 0x3FFFFFFFu) : m;
        if (w < 7) { if (lane == 0) cntS[wb * 8 + w] = __popc(mseg); }
        if (n >= 222) zhi[wb * 36 + (n - 222)] = zf;

        float new_lsd = __fmul_rn(__fadd_rn(lsd, 1.f), __fadd_rn(1.f, -zf));
        float v_sc    = __fdividef(__fadd_rn(new_v, -thr), thr);
        __syncthreads();

        // outputs [4, T, B, N]
        const size_t ob = ((size_t)t * B_ + b) * N_ + n;
        __stcs(out + ob,            zf);
        __stcs(out + TBN_ + ob,     new_v);
        __stcs(out + 2 * TBN_ + ob, thr);
        __stcs(out + 3 * TBN_ + ob, v_sc);

        // phase 2: prefix + flat write + sentinels
        {
            int4 cA = *(const int4*)&cntS[wb * 8];
            int4 cB = *(const int4*)&cntS[wb * 8 + 4];
            if (w < 7) {
                int start = 0;
                if (w > 0) start += cA.x; if (w > 1) start += cA.y;
                if (w > 2) start += cA.z; if (w > 3) start += cA.w;
                if (w > 4) start += cB.x; if (w > 5) start += cB.y;
                if ((mseg >> lane) & 1u) {
                    int r = __popc(mseg & ((1u << lane) - 1u));
                    flatL[wb * LCAP + start + r] = n << 10;
                }
            } else {
                int tt = cA.x + cA.y + cA.z + cA.w + cB.x + cB.y + cB.z;
                if (lane < 8 || tt + lane < 32)
                    flatL[wb * LCAP + tt + lane] = SENT;
                if (lane == 0) totS[wb] = tt;
            }
        }

        z_self = zf; v = new_v; a = new_a; lsd = new_lsd;
        xw_c = xw_n1; xw_n1 = xw_n2;
        __syncthreads();
    }
#undef XW_LD
}

// ---------------------------------------------------------------------------
// Launcher (graph-capturable)
// ---------------------------------------------------------------------------
extern "C" void kernel_launch(void* const* d_in, const int* in_sizes, int n_in,
                              void* d_out, int out_size)
{
    const float* x     = (const float*)d_in[0];
    const float* w_in  = (const float*)d_in[1];
    const float* w_rec = (const float*)d_in[2];
    const float* z0    = (const float*)d_in[3];
    const float* v0    = (const float*)d_in[4];
    const float* a0    = (const float*)d_in[5];
    const float* lsd0  = (const float*)d_in[6];
    float* out = (float*)d_out;

    const float decay_v = expf(-1.0f / 20.0f);
    const float decay_a = expf(-1.0f / 20.0f);

    cudaFuncSetAttribute(gemm_xw,
                         cudaFuncAttributeMaxDynamicSharedMemorySize, GEMM_SMEM);
    cudaFuncSetAttribute(lsnn_scan,
                         cudaFuncAttributeMaxDynamicSharedMemorySize, SCAN_SMEM);

    dim3 g1(M_ / 128, 2);
    gemm_xw<<<g1, 256, GEMM_SMEM>>>(x, w_in);
    lsnn_scan<<<B_, 256, SCAN_SMEM>>>(w_rec, z0, v0, a0, lsd0, out,
                                      decay_v, decay_a);
}